// round 15
// baseline (speedup 1.0000x reference)
#include <cuda_runtime.h>
#include <cuda_bf16.h>

// Word2MatEncoder: out[b] = prod_{s=0..127} M(sent[b][s]), M = 28x28 fp32.
// Associative split: 8 segments of 16 per chain (phase1, 4096 warp-tasks),
// then combine 8 partials per chain (phase2, 512 warp-tasks).
// Inner product: packed fp32 FFMA2 (fma.rn.f32x2), k=0 peeled to mul.rn.f32x2.
// Lane tile = 4 rows x 7 cols (28 active lanes).
// R7+ fix under test: kill register spills (R6 measured regs=127 -> L1 47%).
//   - next-row prefetch via cp.async gmem->smem (wraw), zero register residency
//   - W restaged from wraw with lane=column, offsets affine in k (no offset table)
//   - at-writeback issued BEFORE cp.async wait (hides gather tail)
// R13 fix: __syncwarp() between CP_WAIT0 and stage_wd — cp.async wait only
//   covers the issuing lane's copies; stage_wd reads cross-lane bytes.
// A transposed in smem (36-float rows) -> 1x LDS.128 per k per lane.
// W duplicated in smem (per-cc 20-float groups, 76-float rows)
// -> 3x LDS.128 + 1x LDS.64 per k per lane.

#define MD 28
#define DIM 784
#define SEQ 128
#define SEGS 8
#define SEG_LEN 16
#define BATCH 512
#define WPB 2              // warps per block (2 x 15.68 KB static smem)
#define AT_S 36            // floats per transposed-A row (k-major), 16B-aligned
#define WD_S 76            // floats per duplicated-W row (k-major), 16B-aligned
#define WD_G 20            // floats per cc-group inside a W row

// phase-1 partial products: 512*8*784 floats = 12.8 MB static device scratch
__device__ float g_partial[BATCH * SEGS * DIM];

#define FFMA2(d, a, b, c) \
    asm("fma.rn.f32x2 %0, %1, %2, %3;" : "=l"(d) : "l"(a), "l"(b), "l"(c))
#define FMUL2(d, a, b) \
    asm("mul.rn.f32x2 %0, %1, %2;" : "=l"(d) : "l"(a), "l"(b))
#define CP_ASYNC16(dst_smem_u32, src_gmem) \
    asm volatile("cp.async.cg.shared.global [%0], [%1], 16;" \
                 :: "r"(dst_smem_u32), "l"(src_gmem))
#define CP_COMMIT()  asm volatile("cp.async.commit_group;")
#define CP_WAIT0()   asm volatile("cp.async.wait_group 0;")

union F2U { unsigned long long u; float2 f; };
union F4U { float4 f; unsigned long long u[2]; };

struct alignas(16) WarpSmem {
    float at[MD * AT_S];    // at[k*36 + i] = A[i][k]   (A = running product)  4032 B
    float wd[MD * WD_S];    // wd[k*76 + 20*cc + 2*j(+1)] = W[k][7cc+j] dup    8512 B
    float wraw[DIM];        // raw next-row landing buffer (cp.async)          3136 B
};

template <int NSTEPS, bool P1>
__global__ void __launch_bounds__(WPB * 32)
chain_kernel(const int* __restrict__ sent, const float* __restrict__ table,
             float* __restrict__ out)
{
    __shared__ WarpSmem sm[WPB];
    const int warp = threadIdx.x >> 5;
    const int lane = threadIdx.x & 31;
    const int task = blockIdx.x * WPB + warp;
    WarpSmem& S = sm[warp];

    const int rg = lane >> 2;   // row group 0..6 -> rows 4rg .. 4rg+3
    const int cc = lane & 3;    // col group 0..3 -> cols 7cc .. 7cc+6
    const bool act = lane < 28;

    // staging role: lane == column c (28 active); offsets affine in k
    const int c = lane;
    const int wd_c_off = WD_G * (c / 7) + 2 * (c % 7);   // lane-constant

    const unsigned wraw_u32 = (unsigned)__cvta_generic_to_shared(S.wraw);

    auto rowptr = [&](int t) -> const float* {
        if (P1) {
            int b = task / SEGS, seg = task % SEGS;
            int idx = __ldg(&sent[b * SEQ + seg * SEG_LEN + t]);
            return table + (size_t)idx * DIM;
        } else {
            return g_partial + (size_t)(task * SEGS + t) * DIM;
        }
    };

    // issue async copy of one 3136B row into wraw (no registers held)
    auto issue_row = [&](const float* __restrict__ row) {
#pragma unroll
        for (int m = 0; m < 7; ++m) {
            int i4 = lane + 32 * m;                 // 196 16B-chunks per row
            if (i4 < 196) CP_ASYNC16(wraw_u32 + i4 * 16, row + i4 * 4);
        }
        CP_COMMIT();
    };

    // stage wraw into duplicated-W layout (lane = column c)
    auto stage_wd = [&]() {
        if (act) {
#pragma unroll
            for (int k = 0; k < MD; ++k) {
                float w = S.wraw[k * MD + c];
                *reinterpret_cast<float2*>(&S.wd[k * WD_S + wd_c_off]) =
                    make_float2(w, w);
            }
        }
    };

    // ---- init: at = transpose(M0), wd = W1 ----
    issue_row(rowptr(0));
    CP_WAIT0(); __syncwarp();
    if (act) {
#pragma unroll
        for (int i = 0; i < MD; ++i)
            S.at[c * AT_S + i] = S.wraw[i * MD + c];   // at[j=c][i] = M0[i][j]
    }
    __syncwarp();              // all reads of wraw retired before re-filling it
    issue_row(rowptr(1));
    CP_WAIT0(); __syncwarp();
    stage_wd();
    __syncwarp();

    float* outrow = P1 ? (g_partial + (size_t)task * DIM)
                       : (out + (size_t)task * DIM);

#pragma unroll 1
    for (int t = 1; t < NSTEPS; ++t) {
        const bool havenext = (t + 1 < NSTEPS);

        if (havenext) issue_row(rowptr(t + 1));   // overlaps with compute, 0 regs

        unsigned long long acc[2][7];

        if (act) {
            const float* at = S.at;
            const float* wd = S.wd;
#pragma unroll
            for (int k = 0; k < MD; ++k) {
                // 4 rows of A at column k: one LDS.128 (broadcast across cc lanes)
                F4U a; a.f = *reinterpret_cast<const float4*>(&at[k * AT_S + 4 * rg]);
                const unsigned long long a01 = a.u[0];
                const unsigned long long a23 = a.u[1];
                // 7 duplicated W pairs: 3x LDS.128 + 1x LDS.64 (broadcast across rg)
                const float* wp = &wd[k * WD_S + WD_G * cc];
                F4U w01; w01.f = *reinterpret_cast<const float4*>(wp);       // w0,w0,w1,w1
                F4U w23; w23.f = *reinterpret_cast<const float4*>(wp + 4);   // w2,w2,w3,w3
                F4U w45; w45.f = *reinterpret_cast<const float4*>(wp + 8);   // w4,w4,w5,w5
                const unsigned long long w6 =
                    *reinterpret_cast<const unsigned long long*>(wp + 12);   // w6,w6

                if (k == 0) {
                    FMUL2(acc[0][0], a01, w01.u[0]);
                    FMUL2(acc[1][0], a23, w01.u[0]);
                    FMUL2(acc[0][1], a01, w01.u[1]);
                    FMUL2(acc[1][1], a23, w01.u[1]);
                    FMUL2(acc[0][2], a01, w23.u[0]);
                    FMUL2(acc[1][2], a23, w23.u[0]);
                    FMUL2(acc[0][3], a01, w23.u[1]);
                    FMUL2(acc[1][3], a23, w23.u[1]);
                    FMUL2(acc[0][4], a01, w45.u[0]);
                    FMUL2(acc[1][4], a23, w45.u[0]);
                    FMUL2(acc[0][5], a01, w45.u[1]);
                    FMUL2(acc[1][5], a23, w45.u[1]);
                    FMUL2(acc[0][6], a01, w6);
                    FMUL2(acc[1][6], a23, w6);
                } else {
                    FFMA2(acc[0][0], a01, w01.u[0], acc[0][0]);
                    FFMA2(acc[1][0], a23, w01.u[0], acc[1][0]);
                    FFMA2(acc[0][1], a01, w01.u[1], acc[0][1]);
                    FFMA2(acc[1][1], a23, w01.u[1], acc[1][1]);
                    FFMA2(acc[0][2], a01, w23.u[0], acc[0][2]);
                    FFMA2(acc[1][2], a23, w23.u[0], acc[1][2]);
                    FFMA2(acc[0][3], a01, w23.u[1], acc[0][3]);
                    FFMA2(acc[1][3], a23, w23.u[1], acc[1][3]);
                    FFMA2(acc[0][4], a01, w45.u[0], acc[0][4]);
                    FFMA2(acc[1][4], a23, w45.u[0], acc[1][4]);
                    FFMA2(acc[0][5], a01, w45.u[1], acc[0][5]);
                    FFMA2(acc[1][5], a23, w45.u[1], acc[1][5]);
                    FFMA2(acc[0][6], a01, w6,      acc[0][6]);
                    FFMA2(acc[1][6], a23, w6,      acc[1][6]);
                }
            }
        }

        __syncwarp();   // all lanes done reading at/wd before overwrite

        if (havenext) {
            if (act) {
                // at writeback first: independent of the prefetch, hides its tail
#pragma unroll
                for (int j = 0; j < 7; ++j)
#pragma unroll
                    for (int p = 0; p < 2; ++p) {
                        F2U u; u.u = acc[p][j];
                        *reinterpret_cast<float2*>(
                            &S.at[(7 * cc + j) * AT_S + 4 * rg + 2 * p]) = u.f;
                    }
            }
            CP_WAIT0();      // this lane's cp.async copies complete
            __syncwarp();    // cross-lane visibility — stage_wd reads bytes
                             // written by OTHER lanes' cp.async
            stage_wd();      // wd <- W_{t+1}
            __syncwarp();    // writes visible before next compute
        } else if (act) {
            // final step: write row-major result straight from accumulators
#pragma unroll
            for (int p = 0; p < 2; ++p)
#pragma unroll
                for (int j = 0; j < 7; ++j) {
                    F2U u; u.u = acc[p][j];
                    outrow[(4 * rg + 2 * p + 0) * MD + 7 * cc + j] = u.f.x;
                    outrow[(4 * rg + 2 * p + 1) * MD + 7 * cc + j] = u.f.y;
                }
        }
    }
}

extern "C" void kernel_launch(void* const* d_in, const int* in_sizes, int n_in,
                              void* d_out, int out_size)
{
    const int* sent;
    const float* table;
    if (in_sizes[0] == BATCH * SEQ) {
        sent  = (const int*)d_in[0];
        table = (const float*)d_in[1];
    } else {
        sent  = (const int*)d_in[1];
        table = (const float*)d_in[0];
    }
    float* out = (float*)d_out;

    // Phase 1: 4096 segment products (8 per chain, 16 matrices each)
    chain_kernel<SEG_LEN, true><<<(BATCH * SEGS) / WPB, WPB * 32>>>(sent, table, nullptr);
    // Phase 2: combine 8 partials per chain
    chain_kernel<SEGS, false><<<BATCH / WPB, WPB * 32>>>(sent, table, out);
}